// round 12
// baseline (speedup 1.0000x reference)
#include <cuda_runtime.h>
#include <cuda_bf16.h>
#include <stdint.h>

#define N_NODES 100000
#define N_EDGES 640000
#define HID     128
#define EPS     1e-6f

// Scratch (allocation-free rule: __device__ globals)
__device__ float g_c1[HID];
__device__ float g_c2[HID];
__device__ float g_cconst;
__device__ int   g_is64;
__device__ float g_alpha[N_NODES];
__device__ float g_beta[N_NODES];
__device__ float g_n[N_NODES];

// ---------------------------------------------------------------------------
// Fused prep + dtype detection. 1 block, 1024 threads (8-way j split).
// Launched with PDL/PSS and NO dep-sync: it reads only static harness inputs
// and writes scalars nothing upstream touches, so it legally overlaps the
// previous kernel in the stream (the prior replay's k_out) entirely.
// ---------------------------------------------------------------------------
__global__ void k_prep(const float* __restrict__ W,
                       const float* __restrict__ b,
                       const float* __restrict__ att_w,
                       const long long* __restrict__ e64) {
    __shared__ float s1[1024];
    __shared__ float s2[1024];
    int tid  = threadIdx.x;
    int k    = tid & 127;
    int part = tid >> 7;          // 0..7

    float c1 = 0.f, c2 = 0.f;
    int j0 = part * 16;
    #pragma unroll
    for (int j = j0; j < j0 + 16; ++j) {
        float w = W[j * HID + k];           // coalesced across k
        c1 = fmaf(att_w[j],       w, c1);
        c2 = fmaf(att_w[HID + j], w, c2);
    }
    s1[tid] = c1; s2[tid] = c2;
    __syncthreads();

    if (part == 0) {
        float a1 = 0.f, a2 = 0.f;
        #pragma unroll
        for (int p = 0; p < 8; ++p) {
            a1 += s1[k + p * 128];
            a2 += s2[k + p * 128];
        }
        g_c1[k] = a1;
        g_c2[k] = a2;
    }
    __syncthreads();

    if (tid < 128) s1[tid] = (att_w[tid] + att_w[HID + tid]) * b[tid];
    __syncthreads();

    if (tid == 0) {
        float cc = 0.f;
        #pragma unroll 8
        for (int j = 0; j < HID; ++j) cc += s1[j];
        g_cconst = cc;

        // int64-vs-int32 detection (jax x64-disabled trap): int32 pairs read
        // as int64 give src + (dst<<32) >= 2^32 unless dst==0.
        bool is64 = true;
        #pragma unroll
        for (int i = 0; i < 8; ++i) {
            long long v = e64[i];
            if (v < 0 || v >= (long long)N_NODES) is64 = false;
        }
        g_is64 = is64 ? 1 : 0;
    }
}

// ---------------------------------------------------------------------------
// Per-node scalars, TWO nodes per warp (half-warp layout). PDL: x loads are
// issued BEFORE cudaGridDependencySynchronize so they overlap k_prep.
// ---------------------------------------------------------------------------
__global__ void k_node(const float* __restrict__ x) {
    int gw   = (blockIdx.x * blockDim.x + threadIdx.x) >> 5;
    int lane = threadIdx.x & 31;
    int half = lane >> 4;
    int hl   = lane & 15;
    int node = gw * 2 + half;
    if (node >= N_NODES) {
        cudaGridDependencySynchronize();
        return;
    }

    const float4* xr = reinterpret_cast<const float4*>(x + (size_t)node * HID);
    float4 v0 = __ldg(&xr[hl]);
    float4 v1 = __ldg(&xr[hl + 16]);

    // Wait for k_prep's c1/c2/cconst before consuming them.
    cudaGridDependencySynchronize();

    const float4* C1 = reinterpret_cast<const float4*>(g_c1);
    const float4* C2 = reinterpret_cast<const float4*>(g_c2);
    float4 c10 = C1[hl], c11 = C1[hl + 16];
    float4 c20 = C2[hl], c21 = C2[hl + 16];

    float a = v0.x*c10.x + v0.y*c10.y + v0.z*c10.z + v0.w*c10.w
            + v1.x*c11.x + v1.y*c11.y + v1.z*c11.z + v1.w*c11.w;
    float bt = v0.x*c20.x + v0.y*c20.y + v0.z*c20.z + v0.w*c20.w
             + v1.x*c21.x + v1.y*c21.y + v1.z*c21.z + v1.w*c21.w;

    #pragma unroll
    for (int o = 8; o > 0; o >>= 1) {
        a  += __shfl_xor_sync(0xFFFFFFFFu, a,  o);
        bt += __shfl_xor_sync(0xFFFFFFFFu, bt, o);
    }
    if (hl == 0) {
        g_alpha[node] = a;
        g_beta[node]  = bt;
        g_n[node]     = 0.f;
    }
}

// ---------------------------------------------------------------------------
// Per-edge: n[dst] += exp(leaky_relu(alpha[src] + beta[dst] + cconst)).
// 2 edges/thread, 320k threads (~2 full waves) for maximal latency hiding of
// the L2 gathers. Speculative int32-layout prefetch before the dep-sync:
// those loads touch only the first 5.1 MB, in-bounds for BOTH dtypes.
// ---------------------------------------------------------------------------
#define EDGE_U 2
#define EDGE_TOT (N_EDGES / EDGE_U)   // 320000 threads

__global__ void k_edges(const void* __restrict__ e_raw) {
    int t = blockIdx.x * blockDim.x + threadIdx.x;   // grid exact: 1250*256

    // Speculative int32-layout prefetch (always in-bounds).
    const int2* e32 = (const int2*)e_raw;
    int2 sp[EDGE_U];
    #pragma unroll
    for (int u = 0; u < EDGE_U; ++u)
        sp[u] = __ldg(&e32[t + u * EDGE_TOT]);

    cudaGridDependencySynchronize();

    int s[EDGE_U], d[EDGE_U];
    if (g_is64) {
        const longlong2* e = (const longlong2*)e_raw;
        #pragma unroll
        for (int u = 0; u < EDGE_U; ++u) {
            longlong2 v = __ldg(&e[t + u * EDGE_TOT]);
            s[u] = (int)v.x; d[u] = (int)v.y;
        }
    } else {
        #pragma unroll
        for (int u = 0; u < EDGE_U; ++u) {
            s[u] = sp[u].x; d[u] = sp[u].y;
        }
    }

    float a[EDGE_U], bb[EDGE_U];
    #pragma unroll
    for (int u = 0; u < EDGE_U; ++u) {
        a[u]  = __ldg(&g_alpha[s[u]]);
        bb[u] = __ldg(&g_beta[d[u]]);
    }

    float cc = g_cconst;
    #pragma unroll
    for (int u = 0; u < EDGE_U; ++u) {
        float sc = a[u] + bb[u] + cc;
        sc = (sc >= 0.f) ? sc : 0.2f * sc;
        atomicAdd(&g_n[d[u]], __expf(sc));
    }
}

// ---------------------------------------------------------------------------
// Output, TWO nodes per warp. PDL: ONLY the heavy x loads are hoisted before
// the dep-sync (norm_w/b are tiny L2-hits, loading them late keeps regs ~32
// and occupancy high). __stcs stores (proven best for whole-graph time).
// ---------------------------------------------------------------------------
__global__ void k_out(const float* __restrict__ x,
                      const float* __restrict__ norm_w,
                      const float* __restrict__ norm_b,
                      float* __restrict__ out) {
    int gw   = (blockIdx.x * blockDim.x + threadIdx.x) >> 5;
    int lane = threadIdx.x & 31;
    int half = lane >> 4;
    int hl   = lane & 15;
    int node = gw * 2 + half;
    if (node >= N_NODES) {
        cudaGridDependencySynchronize();
        return;
    }

    const float4* xr = reinterpret_cast<const float4*>(x + (size_t)node * HID);
    float4 v0 = __ldg(&xr[hl]);
    float4 v1 = __ldg(&xr[hl + 16]);

    // Wait for k_edges' atomics before reading n.
    cudaGridDependencySynchronize();

    float n = __ldg(&g_n[node]);
    float inv = (n == 0.f) ? 1.f : __frcp_rn(n);

    float4 y0, y1;
    y0.x = fmaxf(v0.x * inv, 0.f) + v0.x;
    y0.y = fmaxf(v0.y * inv, 0.f) + v0.y;
    y0.z = fmaxf(v0.z * inv, 0.f) + v0.z;
    y0.w = fmaxf(v0.w * inv, 0.f) + v0.w;
    y1.x = fmaxf(v1.x * inv, 0.f) + v1.x;
    y1.y = fmaxf(v1.y * inv, 0.f) + v1.y;
    y1.z = fmaxf(v1.z * inv, 0.f) + v1.z;
    y1.w = fmaxf(v1.w * inv, 0.f) + v1.w;

    float ss = y0.x*y0.x + y0.y*y0.y + y0.z*y0.z + y0.w*y0.w
             + y1.x*y1.x + y1.y*y1.y + y1.z*y1.z + y1.w*y1.w;
    #pragma unroll
    for (int o = 8; o > 0; o >>= 1)
        ss += __shfl_xor_sync(0xFFFFFFFFu, ss, o);

    float inv_rms = rsqrtf(ss * (1.f / (float)HID) + EPS);

    const float4* Wn = reinterpret_cast<const float4*>(norm_w);
    const float4* Bn = reinterpret_cast<const float4*>(norm_b);
    float4 w0 = __ldg(&Wn[hl]),      b0 = __ldg(&Bn[hl]);
    float4 w1 = __ldg(&Wn[hl + 16]), b1 = __ldg(&Bn[hl + 16]);

    float4 o0, o1;
    o0.x = fmaf(w0.x, y0.x * inv_rms, b0.x);
    o0.y = fmaf(w0.y, y0.y * inv_rms, b0.y);
    o0.z = fmaf(w0.z, y0.z * inv_rms, b0.z);
    o0.w = fmaf(w0.w, y0.w * inv_rms, b0.w);
    o1.x = fmaf(w1.x, y1.x * inv_rms, b1.x);
    o1.y = fmaf(w1.y, y1.y * inv_rms, b1.y);
    o1.z = fmaf(w1.z, y1.z * inv_rms, b1.z);
    o1.w = fmaf(w1.w, y1.w * inv_rms, b1.w);

    float4* orow = reinterpret_cast<float4*>(out + (size_t)node * HID);
    __stcs(&orow[hl],      o0);
    __stcs(&orow[hl + 16], o1);
}

// ---------------------------------------------------------------------------
static void launch_pdl(void* fn, dim3 grid, dim3 block, void** args) {
    cudaLaunchConfig_t cfg = {};
    cfg.gridDim  = grid;
    cfg.blockDim = block;
    cfg.stream   = 0;   // legacy default stream (same as <<<>>>)
    cudaLaunchAttribute attr[1];
    attr[0].id = cudaLaunchAttributeProgrammaticStreamSerialization;
    attr[0].val.programmaticStreamSerializationAllowed = 1;
    cfg.attrs    = attr;
    cfg.numAttrs = 1;
    cudaLaunchKernelExC(&cfg, fn, args);
}

extern "C" void kernel_launch(void* const* d_in, const int* in_sizes, int n_in,
                              void* d_out, int out_size) {
    const float* x      = (const float*)d_in[0];
    const float* W      = (const float*)d_in[1];
    const float* b      = (const float*)d_in[2];
    const float* att_w  = (const float*)d_in[3];
    const float* norm_w = (const float*)d_in[4];
    const float* norm_b = (const float*)d_in[5];
    const void*  e      = d_in[6];
    float* out          = (float*)d_out;

    (void)in_sizes; (void)n_in; (void)out_size;

    const long long* e64 = (const long long*)e;
    {   // PDL, no in-kernel dep-sync: overlaps the previous replay's k_out
        void* args[] = { (void*)&W, (void*)&b, (void*)&att_w, (void*)&e64 };
        launch_pdl((void*)k_prep, dim3(1), dim3(1024), args);
    }

    int nwarps  = (N_NODES + 1) / 2;               // 50000 warps
    int nblocks = (nwarps * 32 + 255) / 256;       // 6250

    {
        void* args[] = { (void*)&x };
        launch_pdl((void*)k_node, dim3(nblocks), dim3(256), args);
    }
    {
        int eblocks = (EDGE_TOT + 255) / 256;      // 1250
        void* args[] = { (void*)&e };
        launch_pdl((void*)k_edges, dim3(eblocks), dim3(256), args);
    }
    {
        void* args[] = { (void*)&x, (void*)&norm_w, (void*)&norm_b, (void*)&out };
        launch_pdl((void*)k_out, dim3(nblocks), dim3(256), args);
    }
}

// round 14
// speedup vs baseline: 1.0544x; 1.0544x over previous
#include <cuda_runtime.h>
#include <cuda_bf16.h>
#include <stdint.h>

#define N_NODES 100000
#define N_EDGES 640000
#define HID     128
#define EPS     1e-6f

// Scratch (allocation-free rule: __device__ globals)
__device__ float g_c1[HID];
__device__ float g_c2[HID];
__device__ float g_cconst;
__device__ int   g_is64;
__device__ float g_alpha[N_NODES];
__device__ float g_beta[N_NODES];
__device__ float g_n[N_NODES];

// ---------------------------------------------------------------------------
// Fused prep + dtype detection. 1 block, 1024 threads (8-way j split).
// Launched with PDL/PSS and NO dep-sync: it reads only static harness inputs
// and writes scalars nothing upstream touches, so it legally overlaps the
// previous kernel in the stream (the prior replay's k_out) entirely.
// ---------------------------------------------------------------------------
__global__ void k_prep(const float* __restrict__ W,
                       const float* __restrict__ b,
                       const float* __restrict__ att_w,
                       const long long* __restrict__ e64) {
    __shared__ float s1[1024];
    __shared__ float s2[1024];
    int tid  = threadIdx.x;
    int k    = tid & 127;
    int part = tid >> 7;          // 0..7

    float c1 = 0.f, c2 = 0.f;
    int j0 = part * 16;
    #pragma unroll
    for (int j = j0; j < j0 + 16; ++j) {
        float w = W[j * HID + k];           // coalesced across k
        c1 = fmaf(att_w[j],       w, c1);
        c2 = fmaf(att_w[HID + j], w, c2);
    }
    s1[tid] = c1; s2[tid] = c2;
    __syncthreads();

    if (part == 0) {
        float a1 = 0.f, a2 = 0.f;
        #pragma unroll
        for (int p = 0; p < 8; ++p) {
            a1 += s1[k + p * 128];
            a2 += s2[k + p * 128];
        }
        g_c1[k] = a1;
        g_c2[k] = a2;
    }
    __syncthreads();

    if (tid < 128) s1[tid] = (att_w[tid] + att_w[HID + tid]) * b[tid];
    __syncthreads();

    if (tid == 0) {
        float cc = 0.f;
        #pragma unroll 8
        for (int j = 0; j < HID; ++j) cc += s1[j];
        g_cconst = cc;

        // int64-vs-int32 detection (jax x64-disabled trap): int32 pairs read
        // as int64 give src + (dst<<32) >= 2^32 unless dst==0.
        bool is64 = true;
        #pragma unroll
        for (int i = 0; i < 8; ++i) {
            long long v = e64[i];
            if (v < 0 || v >= (long long)N_NODES) is64 = false;
        }
        g_is64 = is64 ? 1 : 0;
    }
}

// ---------------------------------------------------------------------------
// Per-node scalars, TWO nodes per warp (half-warp layout). PDL: x loads are
// issued BEFORE cudaGridDependencySynchronize so they overlap k_prep.
// ---------------------------------------------------------------------------
__global__ void k_node(const float* __restrict__ x) {
    int gw   = (blockIdx.x * blockDim.x + threadIdx.x) >> 5;
    int lane = threadIdx.x & 31;
    int half = lane >> 4;
    int hl   = lane & 15;
    int node = gw * 2 + half;
    if (node >= N_NODES) {
        cudaGridDependencySynchronize();
        return;
    }

    const float4* xr = reinterpret_cast<const float4*>(x + (size_t)node * HID);
    float4 v0 = __ldg(&xr[hl]);
    float4 v1 = __ldg(&xr[hl + 16]);

    // Wait for k_prep's c1/c2/cconst before consuming them.
    cudaGridDependencySynchronize();

    const float4* C1 = reinterpret_cast<const float4*>(g_c1);
    const float4* C2 = reinterpret_cast<const float4*>(g_c2);
    float4 c10 = C1[hl], c11 = C1[hl + 16];
    float4 c20 = C2[hl], c21 = C2[hl + 16];

    float a = v0.x*c10.x + v0.y*c10.y + v0.z*c10.z + v0.w*c10.w
            + v1.x*c11.x + v1.y*c11.y + v1.z*c11.z + v1.w*c11.w;
    float bt = v0.x*c20.x + v0.y*c20.y + v0.z*c20.z + v0.w*c20.w
             + v1.x*c21.x + v1.y*c21.y + v1.z*c21.z + v1.w*c21.w;

    #pragma unroll
    for (int o = 8; o > 0; o >>= 1) {
        a  += __shfl_xor_sync(0xFFFFFFFFu, a,  o);
        bt += __shfl_xor_sync(0xFFFFFFFFu, bt, o);
    }
    if (hl == 0) {
        g_alpha[node] = a;
        g_beta[node]  = bt;
        g_n[node]     = 0.f;
    }
}

// ---------------------------------------------------------------------------
// Per-edge: n[dst] += exp(leaky_relu(alpha[src] + beta[dst] + cconst)).
// 4 edges/thread, 160k threads (R7/R11-proven sweet spot). Speculative
// int32-layout prefetch before the dep-sync: those loads touch only the
// first 5.1 MB, in-bounds for BOTH dtypes.
// ---------------------------------------------------------------------------
#define EDGE_U 4
#define EDGE_TOT (N_EDGES / EDGE_U)   // 160000 threads

__global__ void k_edges(const void* __restrict__ e_raw) {
    int t = blockIdx.x * blockDim.x + threadIdx.x;   // grid exact: 625*256

    // Speculative int32-layout prefetch (always in-bounds).
    const int2* e32 = (const int2*)e_raw;
    int2 sp[EDGE_U];
    #pragma unroll
    for (int u = 0; u < EDGE_U; ++u)
        sp[u] = __ldg(&e32[t + u * EDGE_TOT]);

    cudaGridDependencySynchronize();

    int s[EDGE_U], d[EDGE_U];
    if (g_is64) {
        const longlong2* e = (const longlong2*)e_raw;
        #pragma unroll
        for (int u = 0; u < EDGE_U; ++u) {
            longlong2 v = __ldg(&e[t + u * EDGE_TOT]);
            s[u] = (int)v.x; d[u] = (int)v.y;
        }
    } else {
        #pragma unroll
        for (int u = 0; u < EDGE_U; ++u) {
            s[u] = sp[u].x; d[u] = sp[u].y;
        }
    }

    float a[EDGE_U], bb[EDGE_U];
    #pragma unroll
    for (int u = 0; u < EDGE_U; ++u) {
        a[u]  = __ldg(&g_alpha[s[u]]);
        bb[u] = __ldg(&g_beta[d[u]]);
    }

    float cc = g_cconst;
    #pragma unroll
    for (int u = 0; u < EDGE_U; ++u) {
        float sc = a[u] + bb[u] + cc;
        sc = (sc >= 0.f) ? sc : 0.2f * sc;
        atomicAdd(&g_n[d[u]], __expf(sc));
    }
}

// ---------------------------------------------------------------------------
// Output, TWO nodes per warp. PDL: ONLY the heavy x loads are hoisted before
// the dep-sync (norm_w/b are tiny L2-hits, loading them late keeps regs ~32
// and occupancy high). __stcs stores (proven best for whole-graph time).
// ---------------------------------------------------------------------------
__global__ void k_out(const float* __restrict__ x,
                      const float* __restrict__ norm_w,
                      const float* __restrict__ norm_b,
                      float* __restrict__ out) {
    int gw   = (blockIdx.x * blockDim.x + threadIdx.x) >> 5;
    int lane = threadIdx.x & 31;
    int half = lane >> 4;
    int hl   = lane & 15;
    int node = gw * 2 + half;
    if (node >= N_NODES) {
        cudaGridDependencySynchronize();
        return;
    }

    const float4* xr = reinterpret_cast<const float4*>(x + (size_t)node * HID);
    float4 v0 = __ldg(&xr[hl]);
    float4 v1 = __ldg(&xr[hl + 16]);

    // Wait for k_edges' atomics before reading n.
    cudaGridDependencySynchronize();

    float n = __ldg(&g_n[node]);
    float inv = (n == 0.f) ? 1.f : __frcp_rn(n);

    float4 y0, y1;
    y0.x = fmaxf(v0.x * inv, 0.f) + v0.x;
    y0.y = fmaxf(v0.y * inv, 0.f) + v0.y;
    y0.z = fmaxf(v0.z * inv, 0.f) + v0.z;
    y0.w = fmaxf(v0.w * inv, 0.f) + v0.w;
    y1.x = fmaxf(v1.x * inv, 0.f) + v1.x;
    y1.y = fmaxf(v1.y * inv, 0.f) + v1.y;
    y1.z = fmaxf(v1.z * inv, 0.f) + v1.z;
    y1.w = fmaxf(v1.w * inv, 0.f) + v1.w;

    float ss = y0.x*y0.x + y0.y*y0.y + y0.z*y0.z + y0.w*y0.w
             + y1.x*y1.x + y1.y*y1.y + y1.z*y1.z + y1.w*y1.w;
    #pragma unroll
    for (int o = 8; o > 0; o >>= 1)
        ss += __shfl_xor_sync(0xFFFFFFFFu, ss, o);

    float inv_rms = rsqrtf(ss * (1.f / (float)HID) + EPS);

    const float4* Wn = reinterpret_cast<const float4*>(norm_w);
    const float4* Bn = reinterpret_cast<const float4*>(norm_b);
    float4 w0 = __ldg(&Wn[hl]),      b0 = __ldg(&Bn[hl]);
    float4 w1 = __ldg(&Wn[hl + 16]), b1 = __ldg(&Bn[hl + 16]);

    float4 o0, o1;
    o0.x = fmaf(w0.x, y0.x * inv_rms, b0.x);
    o0.y = fmaf(w0.y, y0.y * inv_rms, b0.y);
    o0.z = fmaf(w0.z, y0.z * inv_rms, b0.z);
    o0.w = fmaf(w0.w, y0.w * inv_rms, b0.w);
    o1.x = fmaf(w1.x, y1.x * inv_rms, b1.x);
    o1.y = fmaf(w1.y, y1.y * inv_rms, b1.y);
    o1.z = fmaf(w1.z, y1.z * inv_rms, b1.z);
    o1.w = fmaf(w1.w, y1.w * inv_rms, b1.w);

    float4* orow = reinterpret_cast<float4*>(out + (size_t)node * HID);
    __stcs(&orow[hl],      o0);
    __stcs(&orow[hl + 16], o1);
}

// ---------------------------------------------------------------------------
static void launch_pdl(void* fn, dim3 grid, dim3 block, void** args) {
    cudaLaunchConfig_t cfg = {};
    cfg.gridDim  = grid;
    cfg.blockDim = block;
    cfg.stream   = 0;   // legacy default stream (same as <<<>>>)
    cudaLaunchAttribute attr[1];
    attr[0].id = cudaLaunchAttributeProgrammaticStreamSerialization;
    attr[0].val.programmaticStreamSerializationAllowed = 1;
    cfg.attrs    = attr;
    cfg.numAttrs = 1;
    cudaLaunchKernelExC(&cfg, fn, args);
}

extern "C" void kernel_launch(void* const* d_in, const int* in_sizes, int n_in,
                              void* d_out, int out_size) {
    const float* x      = (const float*)d_in[0];
    const float* W      = (const float*)d_in[1];
    const float* b      = (const float*)d_in[2];
    const float* att_w  = (const float*)d_in[3];
    const float* norm_w = (const float*)d_in[4];
    const float* norm_b = (const float*)d_in[5];
    const void*  e      = d_in[6];
    float* out          = (float*)d_out;

    (void)in_sizes; (void)n_in; (void)out_size;

    const long long* e64 = (const long long*)e;
    {   // PDL, no in-kernel dep-sync: overlaps the previous replay's k_out
        void* args[] = { (void*)&W, (void*)&b, (void*)&att_w, (void*)&e64 };
        launch_pdl((void*)k_prep, dim3(1), dim3(1024), args);
    }

    int nwarps  = (N_NODES + 1) / 2;               // 50000 warps
    int nblocks = (nwarps * 32 + 255) / 256;       // 6250

    {
        void* args[] = { (void*)&x };
        launch_pdl((void*)k_node, dim3(nblocks), dim3(256), args);
    }
    {
        int eblocks = (EDGE_TOT + 255) / 256;      // 625
        void* args[] = { (void*)&e };
        launch_pdl((void*)k_edges, dim3(eblocks), dim3(256), args);
    }
    {
        void* args[] = { (void*)&x, (void*)&norm_w, (void*)&norm_b, (void*)&out };
        launch_pdl((void*)k_out, dim3(nblocks), dim3(256), args);
    }
}